// round 1
// baseline (speedup 1.0000x reference)
#include <cuda_runtime.h>
#include <math.h>

// Problem dims (fixed by the reference):
//   x: [B, I, K]      = [32, 2048, 16]
//   W: [1, I, J, D, K]= [1, 2048, 64, 32, 16]
//   out v: [B, J, D]  = [32, 64, 32]
#define BB   32
#define II   2048
#define KK   16
#define JJ   64
#define DD   32
#define JD   (JJ * DD)        // 2048
#define NCHUNK 32
#define IPC  (II / NCHUNK)    // 64 i's per chunk

// Scratch (sanctioned __device__ globals; no cudaMalloc anywhere).
__device__ float g_uhat[(size_t)II * BB * JD];      // [i][b][j*32+d]  512 MB
__device__ float g_spart[BB * NCHUNK * JD];         // [b][chunk][jd]    8 MB
__device__ float g_v[BB * JD];                      // [b][j*32+d]
__device__ float g_logits[(size_t)BB * II * JJ];    // [b][i][j]        16 MB

// ---------------------------------------------------------------------------
// K1: u_hat[i][b][p] = sum_k W[i, p, k] * x[b, i, k],  p = j*32 + d
// One CTA per i. 256 threads, 8 (j,d) pairs each, all 32 b per pair.
// ---------------------------------------------------------------------------
__global__ void __launch_bounds__(256) k_uhat(const float* __restrict__ x,
                                              const float* __restrict__ W) {
    const int i   = blockIdx.x;
    const int tid = threadIdx.x;

    __shared__ float xs[BB * KK];   // x[:, i, :]  (2 KB)
    for (int t = tid; t < BB * KK; t += 256) {
        int b = t >> 4, k = t & 15;
        xs[t] = x[(size_t)b * (II * KK) + (size_t)i * KK + k];
    }
    __syncthreads();

    const float* Wi = W + (size_t)i * (JD * KK);
    float* out = g_uhat + (size_t)i * (BB * JD);

    #pragma unroll
    for (int q = 0; q < 8; ++q) {
        const int p = q * 256 + tid;
        const float4* wp = reinterpret_cast<const float4*>(Wi + (size_t)p * KK);
        float4 w0 = wp[0], w1 = wp[1], w2 = wp[2], w3 = wp[3];

        #pragma unroll 4
        for (int b = 0; b < BB; ++b) {
            const float* xb = xs + b * KK;
            float u = w0.x * xb[0]  + w0.y * xb[1]  + w0.z * xb[2]  + w0.w * xb[3]
                    + w1.x * xb[4]  + w1.y * xb[5]  + w1.z * xb[6]  + w1.w * xb[7]
                    + w2.x * xb[8]  + w2.y * xb[9]  + w2.z * xb[10] + w2.w * xb[11]
                    + w3.x * xb[12] + w3.y * xb[13] + w3.z * xb[14] + w3.w * xb[15];
            out[(size_t)b * JD + p] = u;
        }
    }
}

// ---------------------------------------------------------------------------
// Pass 0: s_partial[b][chunk][e] = sum_{i in chunk} u_hat[i][b][e]
// (uniform routing coeffs; the 1/64 scale is applied in k_squash)
// grid: (NCHUNK, B), block 256; register accumulators, no smem.
// ---------------------------------------------------------------------------
__global__ void __launch_bounds__(256) k_pass0() {
    const int ch  = blockIdx.x;
    const int b   = blockIdx.y;
    const int tid = threadIdx.x;

    float s[8];
    #pragma unroll
    for (int q = 0; q < 8; ++q) s[q] = 0.f;

    const float* base = g_uhat + (size_t)(ch * IPC) * (BB * JD) + (size_t)b * JD;
    for (int ii = 0; ii < IPC; ++ii) {
        const float* row = base + (size_t)ii * (BB * JD);
        #pragma unroll
        for (int q = 0; q < 8; ++q) s[q] += row[q * 256 + tid];
    }

    float* sp = g_spart + ((size_t)b * NCHUNK + ch) * JD;
    #pragma unroll
    for (int q = 0; q < 8; ++q) sp[q * 256 + tid] = s[q];
}

// ---------------------------------------------------------------------------
// Passes 1 & 2: per (b, i):
//   agr[j] = sum_d u_hat[b,i,j,d] * v[b,j,d]
//   logits = agr (addPrev=0, also stored) or g_logits + agr (addPrev=1)
//   c      = softmax_j(logits)
//   s_partial += c[j] * u_hat[b,i,j,d]
// grid: (NCHUNK, B), block 256.
// ---------------------------------------------------------------------------
__global__ void __launch_bounds__(256) k_pass12(int addPrev) {
    const int ch  = blockIdx.x;
    const int b   = blockIdx.y;
    const int tid = threadIdx.x;

    __shared__ float vs[JD];     // v[b,:,:]
    __shared__ float uh[JD];     // u_hat[b,i,:,:]
    __shared__ float lg[JJ];     // logits
    __shared__ float cs[JJ];     // exp(logits - max)

    for (int t = tid; t < JD; t += 256) vs[t] = g_v[(size_t)b * JD + t];

    float s[8];
    #pragma unroll
    for (int q = 0; q < 8; ++q) s[q] = 0.f;

    __syncthreads();

    for (int ii = 0; ii < IPC; ++ii) {
        const int i = ch * IPC + ii;
        const float* row = g_uhat + (size_t)i * (BB * JD) + (size_t)b * JD;
        #pragma unroll
        for (int q = 0; q < 8; ++q) uh[q * 256 + tid] = row[q * 256 + tid];
        __syncthreads();

        // agreement: 64 threads, one j each; rotated d to avoid 32-way bank conflicts
        if (tid < JJ) {
            const int j = tid;
            float a = 0.f;
            #pragma unroll
            for (int dd = 0; dd < DD; ++dd) {
                const int d = (dd + j) & 31;
                a += uh[j * 32 + d] * vs[j * 32 + d];
            }
            float* Lp = g_logits + ((size_t)b * II + i) * JJ + j;
            if (addPrev) a += *Lp;   // b = a0 + a1
            else         *Lp = a;    // store a0 for the next pass
            lg[j] = a;
        }
        __syncthreads();

        if (tid < JJ) {
            float m = -1e30f;
            #pragma unroll 8
            for (int j2 = 0; j2 < JJ; ++j2) m = fmaxf(m, lg[j2]);
            cs[tid] = expf(lg[tid] - m);
        }
        __syncthreads();

        float sum = 0.f;
        #pragma unroll 8
        for (int j2 = 0; j2 < JJ; ++j2) sum += cs[j2];
        const float inv = 1.f / sum;

        #pragma unroll
        for (int q = 0; q < 8; ++q) {
            const int e = q * 256 + tid;
            s[q] += cs[e >> 5] * inv * uh[e];
        }
        __syncthreads();
    }

    float* sp = g_spart + ((size_t)b * NCHUNK + ch) * JD;
    #pragma unroll
    for (int q = 0; q < 8; ++q) sp[q * 256 + tid] = s[q];
}

// ---------------------------------------------------------------------------
// Squash: one 32-thread block per (b,j) row. Deterministic chunk reduction,
// then v = (sq/(1+sq)) * s / sqrt(sq + 1e-8). Writes g_v and optionally d_out.
// ---------------------------------------------------------------------------
__global__ void k_squash(float prescale, float* __restrict__ out) {
    const int row = blockIdx.x;          // b*64 + j
    const int d   = threadIdx.x;         // 0..31
    const int b   = row >> 6;
    const int j   = row & 63;

    const float* sp = g_spart + (size_t)b * NCHUNK * JD + j * 32 + d;
    float sv = 0.f;
    #pragma unroll 8
    for (int ch = 0; ch < NCHUNK; ++ch) sv += sp[(size_t)ch * JD];
    sv *= prescale;

    float sq = sv * sv;
    #pragma unroll
    for (int o = 16; o > 0; o >>= 1) sq += __shfl_xor_sync(0xffffffffu, sq, o);

    const float scale = sq / (1.f + sq);
    const float v = scale * sv / sqrtf(sq + 1e-8f);

    g_v[(size_t)row * 32 + d] = v;
    if (out) out[(size_t)row * 32 + d] = v;
}

// ---------------------------------------------------------------------------
extern "C" void kernel_launch(void* const* d_in, const int* in_sizes, int n_in,
                              void* d_out, int out_size) {
    (void)n_in; (void)out_size;
    const float* x = (const float*)d_in[0];
    const float* W = (const float*)d_in[1];
    // Defensive: x has 1,048,576 elems, W has 67,108,864 — swap if order differs.
    if (in_sizes[0] > in_sizes[1]) { const float* t = x; x = W; W = t; }

    float* out = (float*)d_out;

    k_uhat<<<II, 256>>>(x, W);

    // iteration 0: uniform c = 1/64
    k_pass0<<<dim3(NCHUNK, BB), 256>>>();
    k_squash<<<BB * JJ, 32>>>(1.0f / 64.0f, nullptr);        // v0

    // iteration 1: logits = a0 (stored), c = softmax(a0)
    k_pass12<<<dim3(NCHUNK, BB), 256>>>(0);
    k_squash<<<BB * JJ, 32>>>(1.0f, nullptr);                // v1

    // iteration 2: logits = a0 + a1, c = softmax(a0 + a1)
    k_pass12<<<dim3(NCHUNK, BB), 256>>>(1);
    k_squash<<<BB * JJ, 32>>>(1.0f, out);                    // v2 -> d_out
}

// round 3
// speedup vs baseline: 1.4219x; 1.4219x over previous
#include <cuda_runtime.h>
#include <cstdint>
#include <math.h>

// x: [B, I, K] = [32, 2048, 16]
// W: [1, I, J, D, K] = [1, 2048, 64, 32, 16]
// v: [B, J, D] = [32, 64, 32]
#define BB   32
#define II   2048
#define KK   16
#define JJ   64
#define DD   32
#define JD   (JJ * DD)        // 2048
#define NCHUNK 32
#define IPC  (II / NCHUNK)    // 64

__device__ float g_uhat[(size_t)II * BB * JD];      // [i][b][p], p=j*32+d  (512 MB)
__device__ float g_spart[BB * NCHUNK * JD];         // [b][chunk][p]
__device__ float g_v[BB * JD];
__device__ float g_logits[(size_t)BB * II * JJ];    // [b][i][j]

// ---------------- cp.async helpers ----------------
__device__ __forceinline__ void cp_async16(void* smem_ptr, const void* gptr) {
    unsigned int saddr = (unsigned int)__cvta_generic_to_shared(smem_ptr);
    asm volatile("cp.async.cg.shared.global [%0], [%1], 16;\n" :: "r"(saddr), "l"(gptr));
}
__device__ __forceinline__ void cp_commit() {
    asm volatile("cp.async.commit_group;\n" ::: "memory");
}
template <int N>
__device__ __forceinline__ void cp_wait() {
    asm volatile("cp.async.wait_group %0;\n" :: "n"(N) : "memory");
}

// ---------------------------------------------------------------------------
// K1: u_hat[i][b][p] = sum_k W[i, p, k] * x[b, i, k]
// One CTA per i, 256 threads, float4 stores.
// ---------------------------------------------------------------------------
__global__ void __launch_bounds__(256) k_uhat(const float* __restrict__ x,
                                              const float* __restrict__ W) {
    const int i   = blockIdx.x;
    const int tid = threadIdx.x;

    __shared__ float4 xs4[BB * 4];   // x[:, i, :] as float4 (2 KB)
    if (tid < BB * 4) {
        const int b = tid >> 2, k4 = tid & 3;
        xs4[tid] = reinterpret_cast<const float4*>(x)[(size_t)b * (II * 4) + (size_t)i * 4 + k4];
    }
    __syncthreads();

    const float4* W4 = reinterpret_cast<const float4*>(W) + (size_t)i * (JD * 4);
    float* out = g_uhat + (size_t)i * (BB * JD);

    #pragma unroll
    for (int q = 0; q < 2; ++q) {
        const int f  = q * 256 + tid;   // output float4 index in [0,512)
        const int p0 = f * 4;

        float4 w[4][4];
        #pragma unroll
        for (int r = 0; r < 4; ++r)
            #pragma unroll
            for (int c = 0; c < 4; ++c)
                w[r][c] = W4[(size_t)(p0 + r) * 4 + c];

        #pragma unroll 4
        for (int b = 0; b < BB; ++b) {
            const float4 xa = xs4[b * 4 + 0];
            const float4 xb = xs4[b * 4 + 1];
            const float4 xc = xs4[b * 4 + 2];
            const float4 xd = xs4[b * 4 + 3];
            float4 o;
            float* op = &o.x;
            #pragma unroll
            for (int r = 0; r < 4; ++r) {
                float u = w[r][0].x * xa.x + w[r][0].y * xa.y + w[r][0].z * xa.z + w[r][0].w * xa.w
                        + w[r][1].x * xb.x + w[r][1].y * xb.y + w[r][1].z * xb.z + w[r][1].w * xb.w
                        + w[r][2].x * xc.x + w[r][2].y * xc.y + w[r][2].z * xc.z + w[r][2].w * xc.w
                        + w[r][3].x * xd.x + w[r][3].y * xd.y + w[r][3].z * xd.z + w[r][3].w * xd.w;
                op[r] = u;
            }
            reinterpret_cast<float4*>(out + (size_t)b * JD)[f] = o;
        }
    }
}

// ---------------------------------------------------------------------------
// Pass 0: uniform coefficients — chunk partial sums, float4 streaming.
// grid: (NCHUNK, B), 256 threads.
// ---------------------------------------------------------------------------
__global__ void __launch_bounds__(256) k_pass0() {
    const int ch  = blockIdx.x;
    const int b   = blockIdx.y;
    const int tid = threadIdx.x;

    float4 s0 = make_float4(0.f, 0.f, 0.f, 0.f);
    float4 s1 = make_float4(0.f, 0.f, 0.f, 0.f);

    const float4* base = reinterpret_cast<const float4*>(
        g_uhat + (size_t)(ch * IPC) * (BB * JD) + (size_t)b * JD);
    const size_t stride = (size_t)BB * JD / 4;

    #pragma unroll 4
    for (int ii = 0; ii < IPC; ++ii) {
        const float4 a = base[(size_t)ii * stride + tid];
        const float4 c = base[(size_t)ii * stride + tid + 256];
        s0.x += a.x; s0.y += a.y; s0.z += a.z; s0.w += a.w;
        s1.x += c.x; s1.y += c.y; s1.z += c.z; s1.w += c.w;
    }

    float4* sp = reinterpret_cast<float4*>(g_spart + ((size_t)b * NCHUNK + ch) * JD);
    sp[tid]       = s0;
    sp[tid + 256] = s1;
}

// ---------------------------------------------------------------------------
// Passes 1 & 2: cp.async double-buffered row pipeline.
// grid: (B, NCHUNK), 256 threads.
// ---------------------------------------------------------------------------
__global__ void __launch_bounds__(256) k_pass12(int addPrev) {
    const int b   = blockIdx.x;
    const int ch  = blockIdx.y;
    const int tid = threadIdx.x;

    __shared__ float  vs[JD];          // v[b,:,:]
    __shared__ float4 ub[2][JD / 4];   // double-buffered u rows
    __shared__ float  lg[JJ];
    __shared__ float  cs[JJ];

    for (int t = tid; t < JD; t += 256) vs[t] = g_v[(size_t)b * JD + t];

    float s[8];
    #pragma unroll
    for (int q = 0; q < 8; ++q) s[q] = 0.f;

    const float4* grow0 = reinterpret_cast<const float4*>(
        g_uhat + (size_t)(ch * IPC) * (BB * JD) + (size_t)b * JD);
    const size_t gstride = (size_t)BB * JD / 4;

    float* Lbase = g_logits + ((size_t)b * II + (size_t)ch * IPC) * JJ;

    // prologue: prefetch rows 0 and 1
    cp_async16(&ub[0][tid],       grow0 + tid);
    cp_async16(&ub[0][tid + 256], grow0 + tid + 256);
    cp_commit();
    cp_async16(&ub[1][tid],       grow0 + gstride + tid);
    cp_async16(&ub[1][tid + 256], grow0 + gstride + tid + 256);
    cp_commit();

    float lpf = 0.f;
    if (addPrev && tid < JJ) lpf = Lbase[tid];   // logits for row 0

    for (int ii = 0; ii < IPC; ++ii) {
        if (ii == IPC - 1) cp_wait<0>(); else cp_wait<1>();
        __syncthreads();
        const float* uh = reinterpret_cast<const float*>(ub[ii & 1]);

        // agreement: 64 threads, one j each; rotated d -> conflict-free
        if (tid < JJ) {
            const int j = tid;
            float a = 0.f;
            #pragma unroll
            for (int dd = 0; dd < DD; ++dd) {
                const int d = (dd + j) & 31;
                a += uh[j * 32 + d] * vs[j * 32 + d];
            }
            if (addPrev) a += lpf;
            else         Lbase[(size_t)ii * JJ + j] = a;
            lg[j] = a;
        }
        __syncthreads();

        if (tid < JJ) {
            float m = -1e30f;
            #pragma unroll 8
            for (int j2 = 0; j2 < JJ; ++j2) m = fmaxf(m, lg[j2]);
            cs[tid] = __expf(lg[tid] - m);
        }
        __syncthreads();

        float sum = 0.f;
        #pragma unroll 8
        for (int j2 = 0; j2 < JJ; ++j2) sum += cs[j2];
        const float inv = 1.f / sum;

        #pragma unroll
        for (int q = 0; q < 8; ++q) {
            const int e = q * 256 + tid;
            s[q] += cs[q * 8 + (tid >> 5)] * inv * uh[e];
        }

        // prefetch next row's logits operand off the critical path
        if (addPrev && tid < JJ && ii + 1 < IPC) lpf = Lbase[(size_t)(ii + 1) * JJ + tid];

        __syncthreads();   // all reads of ub[ii&1] done before refill

        if (ii + 2 < IPC) {
            const float4* gr = grow0 + (size_t)(ii + 2) * gstride;
            cp_async16(&ub[ii & 1][tid],       gr + tid);
            cp_async16(&ub[ii & 1][tid + 256], gr + tid + 256);
            cp_commit();
        }
    }

    float* sp = g_spart + ((size_t)b * NCHUNK + ch) * JD;
    #pragma unroll
    for (int q = 0; q < 8; ++q) sp[q * 256 + tid] = s[q];
}

// ---------------------------------------------------------------------------
// Squash: one 32-thread block per (b,j).
// ---------------------------------------------------------------------------
__global__ void k_squash(float prescale, float* __restrict__ out) {
    const int row = blockIdx.x;          // b*64 + j
    const int d   = threadIdx.x;
    const int b   = row >> 6;
    const int j   = row & 63;

    const float* sp = g_spart + (size_t)b * NCHUNK * JD + j * 32 + d;
    float sv = 0.f;
    #pragma unroll 8
    for (int ch = 0; ch < NCHUNK; ++ch) sv += sp[(size_t)ch * JD];
    sv *= prescale;

    float sq = sv * sv;
    #pragma unroll
    for (int o = 16; o > 0; o >>= 1) sq += __shfl_xor_sync(0xffffffffu, sq, o);

    const float scale = sq / (1.f + sq);
    const float v = scale * sv / sqrtf(sq + 1e-8f);

    g_v[(size_t)row * 32 + d] = v;
    if (out) out[(size_t)row * 32 + d] = v;
}

// ---------------------------------------------------------------------------
extern "C" void kernel_launch(void* const* d_in, const int* in_sizes, int n_in,
                              void* d_out, int out_size) {
    (void)n_in; (void)out_size;
    const float* x = (const float*)d_in[0];
    const float* W = (const float*)d_in[1];
    if (in_sizes[0] > in_sizes[1]) { const float* t = x; x = W; W = t; }

    float* out = (float*)d_out;

    k_uhat<<<II, 256>>>(x, W);

    k_pass0<<<dim3(NCHUNK, BB), 256>>>();
    k_squash<<<BB * JJ, 32>>>(1.0f / 64.0f, nullptr);        // v0

    k_pass12<<<dim3(BB, NCHUNK), 256>>>(0);
    k_squash<<<BB * JJ, 32>>>(1.0f, nullptr);                // v1

    k_pass12<<<dim3(BB, NCHUNK), 256>>>(1);
    k_squash<<<BB * JJ, 32>>>(1.0f, out);                    // v2 -> d_out
}

// round 4
// speedup vs baseline: 3.0330x; 2.1331x over previous
#include <cuda_runtime.h>
#include <cuda_fp16.h>
#include <cstdint>
#include <math.h>

// x: [B, I, K] = [32, 2048, 16]
// W: [1, I, J, D, K] = [1, 2048, 64, 32, 16]
// v: [B, J, D] = [32, 64, 32]
#define BB   32
#define II   2048
#define KK   16
#define JJ   64
#define DD   32
#define JD   (JJ * DD)        // 2048
#define NCHUNK 32
#define IPC  (II / NCHUNK)    // 64
#define RR   4                // rows per pipeline step
#define STEPS (IPC / RR)      // 16

__device__ __half g_uhat[(size_t)II * BB * JD];     // [i][b][p] fp16 (256 MB)
__device__ float  g_spart[BB * NCHUNK * JD];        // [b][chunk][p] fp32
__device__ float  g_v[BB * JD];
__device__ float  g_logits[(size_t)BB * II * JJ];   // [b][i][j]

// ---------------- cp.async helpers ----------------
__device__ __forceinline__ void cp_async16(void* smem_ptr, const void* gptr) {
    unsigned int saddr = (unsigned int)__cvta_generic_to_shared(smem_ptr);
    asm volatile("cp.async.cg.shared.global [%0], [%1], 16;\n" :: "r"(saddr), "l"(gptr));
}
__device__ __forceinline__ void cp_commit() {
    asm volatile("cp.async.commit_group;\n" ::: "memory");
}
template <int N>
__device__ __forceinline__ void cp_wait() {
    asm volatile("cp.async.wait_group %0;\n" :: "n"(N) : "memory");
}

// ---------------------------------------------------------------------------
// K1: u_hat[i][b][p] = sum_k W[i, p, k] * x[b, i, k], fp16 output.
// One CTA per i, 256 threads.
// ---------------------------------------------------------------------------
__global__ void __launch_bounds__(256) k_uhat(const float* __restrict__ x,
                                              const float* __restrict__ W) {
    const int i   = blockIdx.x;
    const int tid = threadIdx.x;

    __shared__ float4 xs4[BB * 4];   // x[:, i, :] as float4
    if (tid < BB * 4) {
        const int b = tid >> 2, k4 = tid & 3;
        xs4[tid] = reinterpret_cast<const float4*>(x)[(size_t)b * (II * 4) + (size_t)i * 4 + k4];
    }
    __syncthreads();

    const float4* W4 = reinterpret_cast<const float4*>(W) + (size_t)i * (JD * 4);
    __half* out = g_uhat + (size_t)i * (BB * JD);

    #pragma unroll
    for (int q = 0; q < 2; ++q) {
        const int f  = q * 256 + tid;   // group of 4 outputs, f in [0,512)
        const int p0 = f * 4;

        float4 w[4][4];
        #pragma unroll
        for (int r = 0; r < 4; ++r)
            #pragma unroll
            for (int c = 0; c < 4; ++c)
                w[r][c] = W4[(size_t)(p0 + r) * 4 + c];

        #pragma unroll 4
        for (int b = 0; b < BB; ++b) {
            const float4 xa = xs4[b * 4 + 0];
            const float4 xb = xs4[b * 4 + 1];
            const float4 xc = xs4[b * 4 + 2];
            const float4 xd = xs4[b * 4 + 3];
            float u[4];
            #pragma unroll
            for (int r = 0; r < 4; ++r) {
                u[r] = w[r][0].x * xa.x + w[r][0].y * xa.y + w[r][0].z * xa.z + w[r][0].w * xa.w
                     + w[r][1].x * xb.x + w[r][1].y * xb.y + w[r][1].z * xb.z + w[r][1].w * xb.w
                     + w[r][2].x * xc.x + w[r][2].y * xc.y + w[r][2].z * xc.z + w[r][2].w * xc.w
                     + w[r][3].x * xd.x + w[r][3].y * xd.y + w[r][3].z * xd.z + w[r][3].w * xd.w;
            }
            __half2 h0 = __floats2half2_rn(u[0], u[1]);
            __half2 h1 = __floats2half2_rn(u[2], u[3]);
            uint2 pack;
            pack.x = *reinterpret_cast<unsigned int*>(&h0);
            pack.y = *reinterpret_cast<unsigned int*>(&h1);
            reinterpret_cast<uint2*>(out + (size_t)b * JD)[f] = pack;
        }
    }
}

// ---------------------------------------------------------------------------
// Pass 0: uniform coefficients — chunk partial sums. fp16 in, fp32 out.
// grid: (NCHUNK, B), 256 threads. Thread handles 8 consecutive elements.
// ---------------------------------------------------------------------------
__global__ void __launch_bounds__(256) k_pass0() {
    const int ch  = blockIdx.x;
    const int b   = blockIdx.y;
    const int tid = threadIdx.x;

    float s[8];
    #pragma unroll
    for (int q = 0; q < 8; ++q) s[q] = 0.f;

    const uint4* base = reinterpret_cast<const uint4*>(
        g_uhat + (size_t)(ch * IPC) * (BB * JD) + (size_t)b * JD);
    const size_t stride = (size_t)BB * JD / 8;   // uint4 stride between i rows

    #pragma unroll 4
    for (int ii = 0; ii < IPC; ++ii) {
        const uint4 raw = base[(size_t)ii * stride + tid];
        const __half2* h = reinterpret_cast<const __half2*>(&raw);
        #pragma unroll
        for (int m = 0; m < 4; ++m) {
            const float2 f = __half22float2(h[m]);
            s[2 * m]     += f.x;
            s[2 * m + 1] += f.y;
        }
    }

    float4* sp = reinterpret_cast<float4*>(g_spart + ((size_t)b * NCHUNK + ch) * JD);
    sp[2 * tid]     = make_float4(s[0], s[1], s[2], s[3]);
    sp[2 * tid + 1] = make_float4(s[4], s[5], s[6], s[7]);
}

// ---------------------------------------------------------------------------
// Passes 1 & 2: 4 rows per step, cp.async double-buffered.
// grid: (B, NCHUNK), 256 threads.
// ---------------------------------------------------------------------------
__global__ void __launch_bounds__(256, 4) k_pass12(int addPrev) {
    const int b   = blockIdx.x;
    const int ch  = blockIdx.y;
    const int tid = threadIdx.x;
    const int r   = tid >> 6;    // row in step (0..3)
    const int j   = tid & 63;    // output capsule

    __shared__ float vs[JD];               // v[b,:,:] fp32 (8 KB)
    __shared__ uint4 ub[2][RR][256];       // 2 x 4 rows x 4KB fp16 (32 KB)
    __shared__ float lg[RR][JJ];
    __shared__ float cs[RR][JJ];
    __shared__ float sinv[RR];

    for (int t = tid; t < JD; t += 256) vs[t] = g_v[(size_t)b * JD + t];

    float s[8];
    #pragma unroll
    for (int q = 0; q < 8; ++q) s[q] = 0.f;

    const uint4* grow0 = reinterpret_cast<const uint4*>(
        g_uhat + (size_t)(ch * IPC) * (BB * JD) + (size_t)b * JD);
    const size_t gstride = (size_t)BB * JD / 8;   // uint4 per i row

    float* Lbase = g_logits + ((size_t)b * II + (size_t)ch * IPC) * JJ;  // 64*64 contiguous

    // prologue: prefetch steps 0 and 1 (4 rows each)
    #pragma unroll
    for (int rr = 0; rr < RR; ++rr)
        cp_async16(&ub[0][rr][tid], grow0 + (size_t)rr * gstride + tid);
    cp_commit();
    #pragma unroll
    for (int rr = 0; rr < RR; ++rr)
        cp_async16(&ub[1][rr][tid], grow0 + (size_t)(RR + rr) * gstride + tid);
    cp_commit();

    float lpf = addPrev ? Lbase[tid] : 0.f;   // logits for step 0 (coalesced 256 floats)

    for (int st = 0; st < STEPS; ++st) {
        if (st == STEPS - 1) cp_wait<0>(); else cp_wait<1>();
        __syncthreads();
        const int buf = st & 1;

        // ---- agreement: all 256 threads, one (r,j) each ----
        {
            const __half2* u2 = reinterpret_cast<const __half2*>(ub[buf][r]) + j * 16;
            const float2*  v2 = reinterpret_cast<const float2*>(vs) + j * 16;
            float a = 0.f;
            #pragma unroll
            for (int m = 0; m < 16; ++m) {
                const int m2 = (m + j) & 15;          // rotate to dodge bank conflicts
                const float2 f = __half22float2(u2[m2]);
                const float2 vv = v2[m2];
                a += f.x * vv.x + f.y * vv.y;
            }
            if (addPrev) a += lpf;
            else         Lbase[st * (RR * JJ) + tid] = a;   // coalesced store
            lg[r][j] = a;
        }
        __syncthreads();

        // ---- softmax exp ----
        {
            float m = -1e30f;
            #pragma unroll 8
            for (int j2 = 0; j2 < JJ; ++j2) m = fmaxf(m, lg[r][j2]);
            cs[r][j] = __expf(lg[r][j] - m);
        }
        __syncthreads();

        // ---- per-row inverse sum ----
        {
            float sum = 0.f;
            #pragma unroll 8
            for (int j2 = 0; j2 < JJ; ++j2) sum += cs[r][j2];
            if (j == 0) sinv[r] = 1.f / sum;
        }
        // prefetch next step's logits operand while waiting
        if (addPrev && st + 1 < STEPS) lpf = Lbase[(st + 1) * (RR * JJ) + tid];
        __syncthreads();

        // ---- weighted accumulate: thread handles elements 2h, 2h+1 (h = q*256+tid) ----
        #pragma unroll
        for (int rr = 0; rr < RR; ++rr) {
            const __half2* u2r = reinterpret_cast<const __half2*>(ub[buf][rr]);
            const float iv = sinv[rr];
            #pragma unroll
            for (int q = 0; q < 4; ++q) {
                const int h = q * 256 + tid;          // half2 index in row
                const float c = cs[rr][h >> 4] * iv;  // j = (2h)>>5 = h>>4
                const float2 f = __half22float2(u2r[h]);
                s[2 * q]     += c * f.x;
                s[2 * q + 1] += c * f.y;
            }
        }
        __syncthreads();   // all reads of ub[buf] done before refill

        if (st + 2 < STEPS) {
            const uint4* gr = grow0 + (size_t)(st + 2) * RR * gstride;
            #pragma unroll
            for (int rr = 0; rr < RR; ++rr)
                cp_async16(&ub[buf][rr][tid], gr + (size_t)rr * gstride + tid);
            cp_commit();
        }
    }

    // store partials: element e = 2*(q*256+tid)+{0,1}
    float2* sp = reinterpret_cast<float2*>(g_spart + ((size_t)b * NCHUNK + ch) * JD);
    #pragma unroll
    for (int q = 0; q < 4; ++q)
        sp[q * 256 + tid] = make_float2(s[2 * q], s[2 * q + 1]);
}

// ---------------------------------------------------------------------------
// Squash: one 32-thread block per (b,j).
// ---------------------------------------------------------------------------
__global__ void k_squash(float prescale, float* __restrict__ out) {
    const int row = blockIdx.x;          // b*64 + j
    const int d   = threadIdx.x;
    const int b   = row >> 6;
    const int j   = row & 63;

    const float* sp = g_spart + (size_t)b * NCHUNK * JD + j * 32 + d;
    float sv = 0.f;
    #pragma unroll 8
    for (int ch = 0; ch < NCHUNK; ++ch) sv += sp[(size_t)ch * JD];
    sv *= prescale;

    float sq = sv * sv;
    #pragma unroll
    for (int o = 16; o > 0; o >>= 1) sq += __shfl_xor_sync(0xffffffffu, sq, o);

    const float scale = sq / (1.f + sq);
    const float v = scale * sv / sqrtf(sq + 1e-8f);

    g_v[(size_t)row * 32 + d] = v;
    if (out) out[(size_t)row * 32 + d] = v;
}

// ---------------------------------------------------------------------------
extern "C" void kernel_launch(void* const* d_in, const int* in_sizes, int n_in,
                              void* d_out, int out_size) {
    (void)n_in; (void)out_size;
    const float* x = (const float*)d_in[0];
    const float* W = (const float*)d_in[1];
    if (in_sizes[0] > in_sizes[1]) { const float* t = x; x = W; W = t; }

    float* out = (float*)d_out;

    k_uhat<<<II, 256>>>(x, W);

    k_pass0<<<dim3(NCHUNK, BB), 256>>>();
    k_squash<<<BB * JJ, 32>>>(1.0f / 64.0f, nullptr);        // v0

    k_pass12<<<dim3(BB, NCHUNK), 256>>>(0);
    k_squash<<<BB * JJ, 32>>>(1.0f, nullptr);                // v1

    k_pass12<<<dim3(BB, NCHUNK), 256>>>(1);
    k_squash<<<BB * JJ, 32>>>(1.0f, out);                    // v2 -> d_out
}

// round 5
// speedup vs baseline: 3.5090x; 1.1569x over previous
#include <cuda_runtime.h>
#include <cuda_fp16.h>
#include <cstdint>
#include <math.h>

// x: [B, I, K] = [32, 2048, 16]
// W: [1, I, J, D, K] = [1, 2048, 64, 32, 16]
// v: [B, J, D] = [32, 64, 32]
#define BB   32
#define II   2048
#define KK   16
#define JJ   64
#define DD   32
#define JD   (JJ * DD)        // 2048
#define NCHUNK 32
#define IPC  (II / NCHUNK)    // 64
#define RR   4                // rows per pipeline step
#define STEPS (IPC / RR)      // 16

__device__ __half g_uhat[(size_t)II * BB * JD];     // [i][b][p] fp16 (256 MB)
__device__ float  g_spart[BB * NCHUNK * JD];        // [b][chunk][p] fp32
__device__ float  g_v[BB * JD];
__device__ float  g_logits[(size_t)BB * II * JJ];   // [b][i][j]

// ---------------- cp.async helpers ----------------
__device__ __forceinline__ void cp_async16(void* smem_ptr, const void* gptr) {
    unsigned int saddr = (unsigned int)__cvta_generic_to_shared(smem_ptr);
    asm volatile("cp.async.cg.shared.global [%0], [%1], 16;\n" :: "r"(saddr), "l"(gptr));
}
__device__ __forceinline__ void cp_commit() {
    asm volatile("cp.async.commit_group;\n" ::: "memory");
}
template <int N>
__device__ __forceinline__ void cp_wait() {
    asm volatile("cp.async.wait_group %0;\n" :: "n"(N) : "memory");
}

// ---------------- packed f32x2 helpers ----------------
__device__ __forceinline__ unsigned long long f32x2_mul(unsigned long long a,
                                                        unsigned long long b) {
    unsigned long long d;
    asm("mul.rn.f32x2 %0, %1, %2;" : "=l"(d) : "l"(a), "l"(b));
    return d;
}
__device__ __forceinline__ unsigned long long f32x2_fma(unsigned long long a,
                                                        unsigned long long b,
                                                        unsigned long long c) {
    unsigned long long d;
    asm("fma.rn.f32x2 %0, %1, %2, %3;" : "=l"(d) : "l"(a), "l"(b), "l"(c));
    return d;
}
__device__ __forceinline__ float f32x2_hsum(unsigned long long a) {
    float lo, hi;
    asm("mov.b64 {%0, %1}, %2;" : "=f"(lo), "=f"(hi) : "l"(a));
    return lo + hi;
}

// ---------------------------------------------------------------------------
// K1: u_hat[i][b][p] = sum_k W[i, p, k] * x[b, i, k], fp16 output.
// One CTA per i, 256 threads. Inner dot uses packed fma.rn.f32x2.
// ---------------------------------------------------------------------------
__global__ void __launch_bounds__(256) k_uhat(const float* __restrict__ x,
                                              const float* __restrict__ W) {
    const int i   = blockIdx.x;
    const int tid = threadIdx.x;

    __shared__ ulonglong2 xs2[BB * 4];   // x[:, i, :], 16B chunks (f32x2 pairs)
    if (tid < BB * 4) {
        const int b = tid >> 2, k4 = tid & 3;
        xs2[tid] = reinterpret_cast<const ulonglong2*>(x)[(size_t)b * (II * 4) + (size_t)i * 4 + k4];
    }
    __syncthreads();

    const ulonglong2* W2 = reinterpret_cast<const ulonglong2*>(W) + (size_t)i * (JD * 4);
    __half* out = g_uhat + (size_t)i * (BB * JD);

    #pragma unroll
    for (int q = 0; q < 2; ++q) {
        const int f  = q * 256 + tid;   // group of 4 p's, f in [0,512)
        const int p0 = f * 4;

        ulonglong2 w2[4][4];            // w2[r][c]: p=p0+r, k=4c..4c+3 as 2 f32x2
        #pragma unroll
        for (int r = 0; r < 4; ++r)
            #pragma unroll
            for (int c = 0; c < 4; ++c)
                w2[r][c] = W2[(size_t)(p0 + r) * 4 + c];

        #pragma unroll 2
        for (int b = 0; b < BB; ++b) {
            ulonglong2 xv[4];
            #pragma unroll
            for (int c = 0; c < 4; ++c) xv[c] = xs2[b * 4 + c];

            float u[4];
            #pragma unroll
            for (int r = 0; r < 4; ++r) {
                unsigned long long acc = f32x2_mul(w2[r][0].x, xv[0].x);
                acc = f32x2_fma(w2[r][0].y, xv[0].y, acc);
                acc = f32x2_fma(w2[r][1].x, xv[1].x, acc);
                acc = f32x2_fma(w2[r][1].y, xv[1].y, acc);
                acc = f32x2_fma(w2[r][2].x, xv[2].x, acc);
                acc = f32x2_fma(w2[r][2].y, xv[2].y, acc);
                acc = f32x2_fma(w2[r][3].x, xv[3].x, acc);
                acc = f32x2_fma(w2[r][3].y, xv[3].y, acc);
                u[r] = f32x2_hsum(acc);
            }
            __half2 h0 = __floats2half2_rn(u[0], u[1]);
            __half2 h1 = __floats2half2_rn(u[2], u[3]);
            uint2 pack;
            pack.x = *reinterpret_cast<unsigned int*>(&h0);
            pack.y = *reinterpret_cast<unsigned int*>(&h1);
            reinterpret_cast<uint2*>(out + (size_t)b * JD)[f] = pack;
        }
    }
}

// ---------------------------------------------------------------------------
// Pass 0: uniform coefficients — chunk partial sums. fp16 in, fp32 out.
// ---------------------------------------------------------------------------
__global__ void __launch_bounds__(256) k_pass0() {
    const int ch  = blockIdx.x;
    const int b   = blockIdx.y;
    const int tid = threadIdx.x;

    float s[8];
    #pragma unroll
    for (int q = 0; q < 8; ++q) s[q] = 0.f;

    const uint4* base = reinterpret_cast<const uint4*>(
        g_uhat + (size_t)(ch * IPC) * (BB * JD) + (size_t)b * JD);
    const size_t stride = (size_t)BB * JD / 8;   // uint4 stride between i rows

    #pragma unroll 8
    for (int ii = 0; ii < IPC; ++ii) {
        const uint4 raw = base[(size_t)ii * stride + tid];
        const __half2* h = reinterpret_cast<const __half2*>(&raw);
        #pragma unroll
        for (int m = 0; m < 4; ++m) {
            const float2 f = __half22float2(h[m]);
            s[2 * m]     += f.x;
            s[2 * m + 1] += f.y;
        }
    }

    float4* sp = reinterpret_cast<float4*>(g_spart + ((size_t)b * NCHUNK + ch) * JD);
    sp[2 * tid]     = make_float4(s[0], s[1], s[2], s[3]);
    sp[2 * tid + 1] = make_float4(s[4], s[5], s[6], s[7]);
}

// ---------------------------------------------------------------------------
// Passes 1 & 2: 4 rows per step, cp.async double-buffered, shuffle softmax.
// grid: (B, NCHUNK), 256 threads.
// ---------------------------------------------------------------------------
__global__ void __launch_bounds__(256, 4) k_pass12(int addPrev) {
    const int b   = blockIdx.x;
    const int ch  = blockIdx.y;
    const int tid = threadIdx.x;
    const int r   = tid >> 6;    // row in step (0..3)
    const int j   = tid & 63;    // output capsule
    const int wid = tid >> 5;    // warp id (0..7); row r owns warps 2r, 2r+1

    __shared__ float  vs[JD];              // v[b,:,:] fp32 (8 KB)
    __shared__ uint4  ub[2][RR][256];      // 2 x 4 rows x 4KB fp16 (32 KB)
    __shared__ float2 ms[8];               // per-warp (max, sum)
    __shared__ float  cs[RR][JJ];          // final normalized coeffs

    for (int t = tid; t < JD; t += 256) vs[t] = g_v[(size_t)b * JD + t];

    float s[8];
    #pragma unroll
    for (int q = 0; q < 8; ++q) s[q] = 0.f;

    const uint4* grow0 = reinterpret_cast<const uint4*>(
        g_uhat + (size_t)(ch * IPC) * (BB * JD) + (size_t)b * JD);
    const size_t gstride = (size_t)BB * JD / 8;   // uint4 per i row

    float* Lbase = g_logits + ((size_t)b * II + (size_t)ch * IPC) * JJ;

    // prologue: prefetch steps 0 and 1 (4 rows each)
    #pragma unroll
    for (int rr = 0; rr < RR; ++rr)
        cp_async16(&ub[0][rr][tid], grow0 + (size_t)rr * gstride + tid);
    cp_commit();
    #pragma unroll
    for (int rr = 0; rr < RR; ++rr)
        cp_async16(&ub[1][rr][tid], grow0 + (size_t)(RR + rr) * gstride + tid);
    cp_commit();

    float lpf = addPrev ? Lbase[tid] : 0.f;   // logits for step 0 (coalesced)

    for (int st = 0; st < STEPS; ++st) {
        if (st == STEPS - 1) cp_wait<0>(); else cp_wait<1>();
        __syncthreads();
        const int buf = st & 1;

        // ---- agreement: all 256 threads, one (r,j) each ----
        float a;
        {
            const __half2* u2 = reinterpret_cast<const __half2*>(ub[buf][r]) + j * 16;
            const float2*  v2 = reinterpret_cast<const float2*>(vs) + j * 16;
            a = 0.f;
            #pragma unroll
            for (int m = 0; m < 16; ++m) {
                const int m2 = (m + j) & 15;          // rotate -> conflict-free
                const float2 f = __half22float2(u2[m2]);
                const float2 vv = v2[m2];
                a += f.x * vv.x + f.y * vv.y;
            }
            if (addPrev) a += lpf;
            else         Lbase[st * (RR * JJ) + tid] = a;   // coalesced store
        }

        // ---- shuffle softmax over the row's 64 threads (= 2 warps) ----
        float mw = a;
        #pragma unroll
        for (int o = 16; o > 0; o >>= 1)
            mw = fmaxf(mw, __shfl_xor_sync(0xffffffffu, mw, o));
        const float e = __expf(a - mw);
        float sw = e;
        #pragma unroll
        for (int o = 16; o > 0; o >>= 1)
            sw += __shfl_xor_sync(0xffffffffu, sw, o);
        if ((tid & 31) == 0) ms[wid] = make_float2(mw, sw);
        // prefetch next step's logits while waiting
        if (addPrev && st + 1 < STEPS) lpf = Lbase[(st + 1) * (RR * JJ) + tid];
        __syncthreads();
        {
            const float2 other = ms[wid ^ 1];
            const float M = fmaxf(mw, other.x);
            const float S = sw * __expf(mw - M) + other.y * __expf(other.x - M);
            cs[r][j] = e * __expf(mw - M) / S;       // fully normalized coeff
        }
        __syncthreads();

        // ---- weighted accumulate ----
        #pragma unroll
        for (int rr = 0; rr < RR; ++rr) {
            const __half2* u2r = reinterpret_cast<const __half2*>(ub[buf][rr]);
            #pragma unroll
            for (int q = 0; q < 4; ++q) {
                const int h = q * 256 + tid;          // half2 index in row
                const float c = cs[rr][h >> 4];       // j = h>>4
                const float2 f = __half22float2(u2r[h]);
                s[2 * q]     += c * f.x;
                s[2 * q + 1] += c * f.y;
            }
        }
        __syncthreads();   // all reads of ub[buf] done before refill

        if (st + 2 < STEPS) {
            const uint4* gr = grow0 + (size_t)(st + 2) * RR * gstride;
            #pragma unroll
            for (int rr = 0; rr < RR; ++rr)
                cp_async16(&ub[buf][rr][tid], gr + (size_t)rr * gstride + tid);
            cp_commit();
        }
    }

    float2* sp = reinterpret_cast<float2*>(g_spart + ((size_t)b * NCHUNK + ch) * JD);
    #pragma unroll
    for (int q = 0; q < 4; ++q)
        sp[q * 256 + tid] = make_float2(s[2 * q], s[2 * q + 1]);
}

// ---------------------------------------------------------------------------
// Squash: one 32-thread block per (b,j).
// ---------------------------------------------------------------------------
__global__ void k_squash(float prescale, float* __restrict__ out) {
    const int row = blockIdx.x;          // b*64 + j
    const int d   = threadIdx.x;
    const int b   = row >> 6;
    const int j   = row & 63;

    const float* sp = g_spart + (size_t)b * NCHUNK * JD + j * 32 + d;
    float sv = 0.f;
    #pragma unroll 8
    for (int ch = 0; ch < NCHUNK; ++ch) sv += sp[(size_t)ch * JD];
    sv *= prescale;

    float sq = sv * sv;
    #pragma unroll
    for (int o = 16; o > 0; o >>= 1) sq += __shfl_xor_sync(0xffffffffu, sq, o);

    const float scale = sq / (1.f + sq);
    const float v = scale * sv / sqrtf(sq + 1e-8f);

    g_v[(size_t)row * 32 + d] = v;
    if (out) out[(size_t)row * 32 + d] = v;
}

// ---------------------------------------------------------------------------
extern "C" void kernel_launch(void* const* d_in, const int* in_sizes, int n_in,
                              void* d_out, int out_size) {
    (void)n_in; (void)out_size;
    const float* x = (const float*)d_in[0];
    const float* W = (const float*)d_in[1];
    if (in_sizes[0] > in_sizes[1]) { const float* t = x; x = W; W = t; }

    float* out = (float*)d_out;

    k_uhat<<<II, 256>>>(x, W);

    k_pass0<<<dim3(NCHUNK, BB), 256>>>();
    k_squash<<<BB * JJ, 32>>>(1.0f / 64.0f, nullptr);        // v0

    k_pass12<<<dim3(BB, NCHUNK), 256>>>(0);
    k_squash<<<BB * JJ, 32>>>(1.0f, nullptr);                // v1

    k_pass12<<<dim3(BB, NCHUNK), 256>>>(1);
    k_squash<<<BB * JJ, 32>>>(1.0f, out);                    // v2 -> d_out
}

// round 6
// speedup vs baseline: 3.8827x; 1.1065x over previous
#include <cuda_runtime.h>
#include <cuda_fp16.h>
#include <cstdint>
#include <math.h>

// x: [B, I, K] = [32, 2048, 16]
// W: [1, I, J, D, K] = [1, 2048, 64, 32, 16]
// v: [B, J, D] = [32, 64, 32]
#define BB   32
#define II   2048
#define KK   16
#define JJ   64
#define DD   32
#define JD   (JJ * DD)        // 2048
#define NCHUNK 32
#define IPC  (II / NCHUNK)    // 64
#define RR   4                // rows per pipeline step
#define STEPS (IPC / RR)      // 16

__device__ __half g_uhat[(size_t)II * BB * JD];     // [i][b][p] fp16 (256 MB)
__device__ float  g_spart[BB * NCHUNK * JD];        // [b][chunk][p] fp32
__device__ float  g_v[BB * JD];
__device__ float  g_logits[(size_t)BB * II * JJ];   // [b][i][j]

// ---------------- cp.async helpers ----------------
__device__ __forceinline__ void cp_async16(void* smem_ptr, const void* gptr) {
    unsigned int saddr = (unsigned int)__cvta_generic_to_shared(smem_ptr);
    asm volatile("cp.async.cg.shared.global [%0], [%1], 16;\n" :: "r"(saddr), "l"(gptr));
}
__device__ __forceinline__ void cp_commit() {
    asm volatile("cp.async.commit_group;\n" ::: "memory");
}
template <int N>
__device__ __forceinline__ void cp_wait() {
    asm volatile("cp.async.wait_group %0;\n" :: "n"(N) : "memory");
}

// ---------------- packed f32x2 helpers ----------------
__device__ __forceinline__ unsigned long long f32x2_mul(unsigned long long a,
                                                        unsigned long long b) {
    unsigned long long d;
    asm("mul.rn.f32x2 %0, %1, %2;" : "=l"(d) : "l"(a), "l"(b));
    return d;
}
__device__ __forceinline__ unsigned long long f32x2_fma(unsigned long long a,
                                                        unsigned long long b,
                                                        unsigned long long c) {
    unsigned long long d;
    asm("fma.rn.f32x2 %0, %1, %2, %3;" : "=l"(d) : "l"(a), "l"(b), "l"(c));
    return d;
}
__device__ __forceinline__ float f32x2_hsum(unsigned long long a) {
    float lo, hi;
    asm("mov.b64 {%0, %1}, %2;" : "=f"(lo), "=f"(hi) : "l"(a));
    return lo + hi;
}

// ---------------------------------------------------------------------------
// K1: u_hat[i][b][p] = sum_k W[i, p, k] * x[b, i, k], fp16 output.
// ---------------------------------------------------------------------------
__global__ void __launch_bounds__(256) k_uhat(const float* __restrict__ x,
                                              const float* __restrict__ W) {
    const int i   = blockIdx.x;
    const int tid = threadIdx.x;

    __shared__ ulonglong2 xs2[BB * 4];   // x[:, i, :], 16B chunks (f32x2 pairs)
    if (tid < BB * 4) {
        const int b = tid >> 2, k4 = tid & 3;
        xs2[tid] = reinterpret_cast<const ulonglong2*>(x)[(size_t)b * (II * 4) + (size_t)i * 4 + k4];
    }
    __syncthreads();

    const ulonglong2* W2 = reinterpret_cast<const ulonglong2*>(W) + (size_t)i * (JD * 4);
    __half* out = g_uhat + (size_t)i * (BB * JD);

    #pragma unroll
    for (int q = 0; q < 2; ++q) {
        const int f  = q * 256 + tid;   // group of 4 p's, f in [0,512)
        const int p0 = f * 4;

        ulonglong2 w2[4][4];
        #pragma unroll
        for (int r = 0; r < 4; ++r)
            #pragma unroll
            for (int c = 0; c < 4; ++c)
                w2[r][c] = W2[(size_t)(p0 + r) * 4 + c];

        #pragma unroll 2
        for (int b = 0; b < BB; ++b) {
            ulonglong2 xv[4];
            #pragma unroll
            for (int c = 0; c < 4; ++c) xv[c] = xs2[b * 4 + c];

            float u[4];
            #pragma unroll
            for (int r = 0; r < 4; ++r) {
                unsigned long long acc = f32x2_mul(w2[r][0].x, xv[0].x);
                acc = f32x2_fma(w2[r][0].y, xv[0].y, acc);
                acc = f32x2_fma(w2[r][1].x, xv[1].x, acc);
                acc = f32x2_fma(w2[r][1].y, xv[1].y, acc);
                acc = f32x2_fma(w2[r][2].x, xv[2].x, acc);
                acc = f32x2_fma(w2[r][2].y, xv[2].y, acc);
                acc = f32x2_fma(w2[r][3].x, xv[3].x, acc);
                acc = f32x2_fma(w2[r][3].y, xv[3].y, acc);
                u[r] = f32x2_hsum(acc);
            }
            __half2 h0 = __floats2half2_rn(u[0], u[1]);
            __half2 h1 = __floats2half2_rn(u[2], u[3]);
            uint2 pack;
            pack.x = *reinterpret_cast<unsigned int*>(&h0);
            pack.y = *reinterpret_cast<unsigned int*>(&h1);
            reinterpret_cast<uint2*>(out + (size_t)b * JD)[f] = pack;
        }
    }
}

// ---------------------------------------------------------------------------
// Pass 0: uniform coefficients — chunk partial sums. fp16 in, fp32 out.
// ---------------------------------------------------------------------------
__global__ void __launch_bounds__(256) k_pass0() {
    const int ch  = blockIdx.x;
    const int b   = blockIdx.y;
    const int tid = threadIdx.x;

    float s[8];
    #pragma unroll
    for (int q = 0; q < 8; ++q) s[q] = 0.f;

    const uint4* base = reinterpret_cast<const uint4*>(
        g_uhat + (size_t)(ch * IPC) * (BB * JD) + (size_t)b * JD);
    const size_t stride = (size_t)BB * JD / 8;

    #pragma unroll 8
    for (int ii = 0; ii < IPC; ++ii) {
        const uint4 raw = base[(size_t)ii * stride + tid];
        const __half2* h = reinterpret_cast<const __half2*>(&raw);
        #pragma unroll
        for (int m = 0; m < 4; ++m) {
            const float2 f = __half22float2(h[m]);
            s[2 * m]     += f.x;
            s[2 * m + 1] += f.y;
        }
    }

    float4* sp = reinterpret_cast<float4*>(g_spart + ((size_t)b * NCHUNK + ch) * JD);
    sp[2 * tid]     = make_float4(s[0], s[1], s[2], s[3]);
    sp[2 * tid + 1] = make_float4(s[4], s[5], s[6], s[7]);
}

// ---------------------------------------------------------------------------
// Passes 1 & 2: register-resident u rows, quad-shuffle agreement.
// Thread t owns halves 8t..8t+7 of every row (single j = t>>2).
// grid: (B, NCHUNK), 256 threads.
// ---------------------------------------------------------------------------
__global__ void __launch_bounds__(256, 4) k_pass12(int addPrev) {
    const int b   = blockIdx.x;
    const int ch  = blockIdx.y;
    const int tid = threadIdx.x;
    const int r   = tid >> 6;    // softmax-space row (0..3)
    const int j   = tid & 63;    // softmax-space capsule
    const int wid = tid >> 5;

    __shared__ uint4  ub[2][RR][256];      // 2 x 4 rows x 4KB fp16 (32 KB)
    __shared__ float  lg[JJ * 5];          // [j*5 + rr], padded stride
    __shared__ float  cs[RR][JJ];          // normalized coeffs
    __shared__ float2 ms[8];               // per-warp (max, sum)

    // v in registers: thread t holds v[b, 8t..8t+7]
    float vf[8];
    {
        const float4* gv4 = reinterpret_cast<const float4*>(g_v + (size_t)b * JD);
        const float4 v0 = gv4[2 * tid], v1 = gv4[2 * tid + 1];
        vf[0] = v0.x; vf[1] = v0.y; vf[2] = v0.z; vf[3] = v0.w;
        vf[4] = v1.x; vf[5] = v1.y; vf[6] = v1.z; vf[7] = v1.w;
    }

    float s[8];
    #pragma unroll
    for (int q = 0; q < 8; ++q) s[q] = 0.f;

    const uint4* grow0 = reinterpret_cast<const uint4*>(
        g_uhat + (size_t)(ch * IPC) * (BB * JD) + (size_t)b * JD);
    const size_t gstride = (size_t)BB * JD / 8;   // uint4 per i row

    float* Lbase = g_logits + ((size_t)b * II + (size_t)ch * IPC) * JJ;

    // prologue: prefetch steps 0 and 1
    #pragma unroll
    for (int rr = 0; rr < RR; ++rr)
        cp_async16(&ub[0][rr][tid], grow0 + (size_t)rr * gstride + tid);
    cp_commit();
    #pragma unroll
    for (int rr = 0; rr < RR; ++rr)
        cp_async16(&ub[1][rr][tid], grow0 + (size_t)(RR + rr) * gstride + tid);
    cp_commit();

    float lpf = addPrev ? Lbase[tid] : 0.f;   // logits for step 0 (coalesced)

    for (int st = 0; st < STEPS; ++st) {
        if (st == STEPS - 1) cp_wait<0>(); else cp_wait<1>();
        const int buf = st & 1;

        // pull this step's u into registers (only own-thread data -> no sync)
        uint4 u4[RR];
        #pragma unroll
        for (int rr = 0; rr < RR; ++rr) u4[rr] = ub[buf][rr][tid];

        // refill this buffer immediately (thread t is sole producer+consumer)
        if (st + 2 < STEPS) {
            const uint4* gr = grow0 + (size_t)(st + 2) * RR * gstride;
            #pragma unroll
            for (int rr = 0; rr < RR; ++rr)
                cp_async16(&ub[buf][rr][tid], gr + (size_t)rr * gstride + tid);
            cp_commit();
        }

        // ---- agreement: per-thread 8-FMA partial dot + quad reduce ----
        float a[RR];
        #pragma unroll
        for (int rr = 0; rr < RR; ++rr) {
            const __half2* h = reinterpret_cast<const __half2*>(&u4[rr]);
            float acc = 0.f;
            #pragma unroll
            for (int m = 0; m < 4; ++m) {
                const float2 f = __half22float2(h[m]);
                acc += f.x * vf[2 * m] + f.y * vf[2 * m + 1];
            }
            acc += __shfl_xor_sync(0xffffffffu, acc, 1);
            acc += __shfl_xor_sync(0xffffffffu, acc, 2);
            a[rr] = acc;
        }
        // thread t publishes row (t&3), capsule (t>>2): conflict-free STS
        lg[(tid >> 2) * 5 + (tid & 3)] = a[tid & 3];
        __syncthreads();

        // ---- softmax in (r, j) space ----
        float araw = lg[j * 5 + r];
        if (addPrev) araw += lpf;
        else         Lbase[st * (RR * JJ) + tid] = araw;   // coalesced

        float mw = araw;
        #pragma unroll
        for (int o = 16; o > 0; o >>= 1)
            mw = fmaxf(mw, __shfl_xor_sync(0xffffffffu, mw, o));
        const float e = __expf(araw - mw);
        float sw = e;
        #pragma unroll
        for (int o = 16; o > 0; o >>= 1)
            sw += __shfl_xor_sync(0xffffffffu, sw, o);
        if ((tid & 31) == 0) ms[wid] = make_float2(mw, sw);
        if (addPrev && st + 1 < STEPS) lpf = Lbase[(st + 1) * (RR * JJ) + tid];
        __syncthreads();
        {
            const float2 other = ms[wid ^ 1];
            const float M = fmaxf(mw, other.x);
            const float S = sw * __expf(mw - M) + other.y * __expf(other.x - M);
            cs[r][j] = e * __expf(mw - M) / S;
        }
        __syncthreads();

        // ---- weighted accumulate from registers ----
        #pragma unroll
        for (int rr = 0; rr < RR; ++rr) {
            const float c = cs[rr][tid >> 2];   // broadcast within quad
            const __half2* h = reinterpret_cast<const __half2*>(&u4[rr]);
            #pragma unroll
            for (int m = 0; m < 4; ++m) {
                const float2 f = __half22float2(h[m]);
                s[2 * m]     += c * f.x;
                s[2 * m + 1] += c * f.y;
            }
        }
    }

    // thread t owns p = 8t..8t+7
    float4* sp = reinterpret_cast<float4*>(g_spart + ((size_t)b * NCHUNK + ch) * JD);
    sp[2 * tid]     = make_float4(s[0], s[1], s[2], s[3]);
    sp[2 * tid + 1] = make_float4(s[4], s[5], s[6], s[7]);
}

// ---------------------------------------------------------------------------
// Squash: one 32-thread block per (b,j).
// ---------------------------------------------------------------------------
__global__ void k_squash(float prescale, float* __restrict__ out) {
    const int row = blockIdx.x;          // b*64 + j
    const int d   = threadIdx.x;
    const int b   = row >> 6;
    const int j   = row & 63;

    const float* sp = g_spart + (size_t)b * NCHUNK * JD + j * 32 + d;
    float sv = 0.f;
    #pragma unroll 8
    for (int ch = 0; ch < NCHUNK; ++ch) sv += sp[(size_t)ch * JD];
    sv *= prescale;

    float sq = sv * sv;
    #pragma unroll
    for (int o = 16; o > 0; o >>= 1) sq += __shfl_xor_sync(0xffffffffu, sq, o);

    const float scale = sq / (1.f + sq);
    const float v = scale * sv / sqrtf(sq + 1e-8f);

    g_v[(size_t)row * 32 + d] = v;
    if (out) out[(size_t)row * 32 + d] = v;
}

// ---------------------------------------------------------------------------
extern "C" void kernel_launch(void* const* d_in, const int* in_sizes, int n_in,
                              void* d_out, int out_size) {
    (void)n_in; (void)out_size;
    const float* x = (const float*)d_in[0];
    const float* W = (const float*)d_in[1];
    if (in_sizes[0] > in_sizes[1]) { const float* t = x; x = W; W = t; }

    float* out = (float*)d_out;

    k_uhat<<<II, 256>>>(x, W);

    k_pass0<<<dim3(NCHUNK, BB), 256>>>();
    k_squash<<<BB * JJ, 32>>>(1.0f / 64.0f, nullptr);        // v0

    k_pass12<<<dim3(BB, NCHUNK), 256>>>(0);
    k_squash<<<BB * JJ, 32>>>(1.0f, nullptr);                // v1

    k_pass12<<<dim3(BB, NCHUNK), 256>>>(1);
    k_squash<<<BB * JJ, 32>>>(1.0f, out);                    // v2 -> d_out
}